// round 11
// baseline (speedup 1.0000x reference)
#include <cuda_runtime.h>
#include <cstdint>

// Problem constants
#define NN 128
#define CC 64
#define TT 256
#define VV 25
#define DD 64
#define RR 16           // SE reduction dim (C/4)
#define FEAT 1600       // V*D
#define ROWS (NN*TT)    // 32768
#define TTILE 8         // t-frames per gemm tile
#define NTILES 4        // tiles per block
#define ATSTRIDE 28     // v-dim stride in At (112B rows, 16B-aligned for LDS.128)
#define ATW (CC*ATSTRIDE)   // 1792 floats per warp region

typedef unsigned long long u64;

// ---------------- scratch (device globals; no allocations allowed) ----------
__device__ float g_pooled[NN*CC];
__device__ float g_gate[NN*4];
__device__ float g_Wf[NN*CC*DD];      // 2 MB
__device__ float g_bf[NN*DD];
__device__ float g_z[(size_t)NN*CC*TT*VV]; // 209.7 MB, OUTPUT layout [n][d][t][v], pre-BN
__device__ float g_sum[FEAT];
__device__ float g_sumsq[FEAT];
__device__ float g_scale[FEAT];
__device__ float g_bias[FEAT];
__device__ float2 g_tpack[CC*ATSTRIDE]; // packed gather rec: {tm, bitcast(src)}
__device__ short g_inv[FEAT];           // inv_pad: s -> f+(f>>6)  (= v*65+d)

// ---------------- f32x2 helpers ---------------------------------------------
__device__ __forceinline__ u64 pack2(float lo, float hi) {
    u64 r; asm("mov.b64 %0, {%1, %2};" : "=l"(r) : "f"(lo), "f"(hi)); return r;
}
__device__ __forceinline__ void unpack2(u64 v, float& lo, float& hi) {
    asm("mov.b64 {%0, %1}, %2;" : "=f"(lo), "=f"(hi) : "l"(v));
}
__device__ __forceinline__ u64 ffma2(u64 a, u64 b, u64 c) {
    u64 d; asm("fma.rn.f32x2 %0, %1, %2, %3;" : "=l"(d) : "l"(a), "l"(b), "l"(c));
    return d;
}
__device__ __forceinline__ void cp_async16(float* dst_smem, const void* src) {
    unsigned d = (unsigned)__cvta_generic_to_shared(dst_smem);
    asm volatile("cp.async.cg.shared.global [%0], [%1], 16;" :: "r"(d), "l"(src));
}
#define CP_COMMIT() asm volatile("cp.async.commit_group;")
#define CP_WAIT0()  asm volatile("cp.async.wait_group 0;")

// ---------------- kernel 1: global average pool ------------------------------
__global__ void pool_kernel(const float* __restrict__ x0) {
    int nc = blockIdx.x;
    const float4* p = (const float4*)(x0 + (size_t)nc * (TT*VV));
    float s = 0.f;
    for (int i = threadIdx.x; i < (TT*VV)/4; i += 256) {
        float4 v = p[i];
        s += v.x + v.y + v.z + v.w;
    }
    for (int off = 16; off > 0; off >>= 1) s += __shfl_down_sync(0xffffffffu, s, off);
    __shared__ float red[8];
    int w = threadIdx.x >> 5, l = threadIdx.x & 31;
    if (l == 0) red[w] = s;
    __syncthreads();
    if (threadIdx.x == 0) {
        float t = 0.f;
        #pragma unroll
        for (int i = 0; i < 8; i++) t += red[i];
        g_pooled[nc] = t * (1.f / (TT*VV));
    }
}

// ---------------- kernel 2: SE gate ------------------------------------------
__global__ void gate_kernel(const float* __restrict__ fc1_w, const float* __restrict__ fc1_b,
                            const float* __restrict__ fc2_w, const float* __restrict__ fc2_b,
                            const int* __restrict__ epoch_p) {
    int n = threadIdx.x;
    if (n >= NN) return;
    float pooled[CC];
    #pragma unroll
    for (int c = 0; c < CC; c++) pooled[c] = g_pooled[n*CC + c];
    float h[RR];
    #pragma unroll
    for (int j = 0; j < RR; j++) {
        float s = fc1_b[j];
        #pragma unroll
        for (int c = 0; c < CC; c++) s += pooled[c] * fc1_w[j*CC + c];
        h[j] = s > 0.f ? s : 0.f;
    }
    float lg[4];
    #pragma unroll
    for (int k = 0; k < 4; k++) {
        float s = fc2_b[k];
        #pragma unroll
        for (int j = 0; j < RR; j++) s += h[j] * fc2_w[k*RR + j];
        lg[k] = s;
    }
    int ep = *epoch_p;
    float tao = (ep >= 60) ? 1.0f : (-(29.0f / 60.0f) * (float)ep + 30.0f);
    float inv = 1.0f / tao;
    float m = lg[0];
    #pragma unroll
    for (int k = 1; k < 4; k++) m = fmaxf(m, lg[k]);
    float e[4], sum = 0.f;
    #pragma unroll
    for (int k = 0; k < 4; k++) { e[k] = __expf((lg[k] - m) * inv); sum += e[k]; }
    float r = 1.0f / sum;
    #pragma unroll
    for (int k = 0; k < 4; k++) g_gate[n*4 + k] = e[k] * r;
}

// ---------------- kernel 3: fused weights + tables + zero stats --------------
__global__ void prep_kernel(const float* __restrict__ W, const float* __restrict__ b,
                            const float* __restrict__ mask, const int* __restrict__ shift_in,
                            const int* __restrict__ shift_out) {
    int blk = blockIdx.x;
    int tid = threadIdx.x;
    if (blk < NN) {
        int n = blk;
        float g0 = g_gate[n*4+0], g1 = g_gate[n*4+1], g2 = g_gate[n*4+2], g3 = g_gate[n*4+3];
        for (int i = tid; i < CC*DD; i += 256)
            g_Wf[n*CC*DD + i] = g0*W[i] + g1*W[CC*DD + i] + g2*W[2*CC*DD + i] + g3*W[3*CC*DD + i];
        if (tid < DD)
            g_bf[n*DD + tid] = g0*b[tid] + g1*b[DD+tid] + g2*b[2*DD+tid] + g3*b[3*DD+tid];
    } else {
        for (int j = tid; j < CC*ATSTRIDE; j += 256) {
            int c_out = j / ATSTRIDE, v_out = j % ATSTRIDE;
            float2 rec;
            if (v_out < VV) {
                int src = shift_in[v_out*CC + c_out];
                int vp = src >> 6, cp = src & 63;          // C == 64
                rec.x = tanhf(mask[v_out*CC + c_out]) + 1.0f;
                rec.y = __int_as_float(cp * (TTILE*VV) + vp);
            } else {
                rec.x = 0.f;
                rec.y = __int_as_float(0);
            }
            g_tpack[j] = rec;
        }
        for (int f = tid; f < FEAT; f += 256) {
            g_sum[f] = 0.f; g_sumsq[f] = 0.f;
            int s = shift_out[f];
            g_inv[s] = (short)(f + (f >> 6));       // padded v*65+d offset
        }
    }
}

// ---------------- kernel 4: persistent pipelined GEMM + scatter + stats ------
// 1024 blocks; block = (n = bid>>3, q8 = bid&7); 4 tiles of 8 frames.
// 8 warps; warp w = frame w; lane l owns d-pair (2l, 2l+1), all 25 v.
#define RAW_F (CC*TTILE*VV)        // 12800
#define AT_F  (8*ATW)              // 14336
#define GEMM_SMEM_BYTES ((RAW_F + AT_F + DD)*4 + FEAT*2)

__global__ void __launch_bounds__(256, 2) gemm_kernel(const float* __restrict__ x0) {
    extern __shared__ float smem[];
    float* raw  = smem;                 // [c][t][v] 64 x 200
    float* Ats  = raw + RAW_F;          // 8 x [c][28]; aliased as scatter buf [v*65+d]
    float* bfs  = Ats + AT_F;           // [64]
    short* invs = (short*)(bfs + DD);   // [1600]

    int bid = blockIdx.x;
    int n   = bid >> 3;
    int q8  = bid & 7;
    int tid = threadIdx.x;
    int w = tid >> 5, l = tid & 31;

    { // block-start staging (covered by first loop-top sync)
        for (int f = tid; f < FEAT; f += 256) invs[f] = g_inv[f];
        if (tid < DD) bfs[tid] = g_bf[n*DD + tid];
    }

    const float* xbase = x0 + (size_t)n * CC * (TT*VV);

    // prefetch tile 0
    {
        const float* xb = xbase + (q8*32) * VV;
        #pragma unroll
        for (int k = 0; k < 13; k++) {
            int i = tid + k*256;
            if (i < RAW_F/4) {
                int c = i / 50, qq = i - c*50;
                cp_async16(raw + c*(TTILE*VV) + qq*4, xb + c*(TT*VV) + qq*4);
            }
        }
        CP_COMMIT();
    }

    int d0 = 2*l;
    float* At = Ats + w * ATW;
    const float* rw = raw + w * VV;
    const float* Wg = g_Wf + (size_t)n * (CC*DD) + d0;

    float rsum[7], rsq[7];
    #pragma unroll
    for (int k = 0; k < 7; k++) { rsum[k] = 0.f; rsq[k] = 0.f; }

    for (int it = 0; it < NTILES; it++) {
        int t0 = q8*32 + it*TTILE;
        CP_WAIT0();
        __syncthreads();                       // raw ready; prev epilogue consumed

        // gather + mask into transposed At[c][28] (packed table: one LDG.64/elt)
        {
            const float2* __restrict__ tp = g_tpack;
            #pragma unroll 4
            for (int j = l; j < ATW; j += 32) {
                float2 rec = tp[j];
                At[j] = rw[__float_as_int(rec.y)] * rec.x;
            }
        }
        __syncthreads();                       // raw now free

        // prefetch next tile (DMA overlaps compute)
        if (it + 1 < NTILES) {
            const float* xb = xbase + (t0 + TTILE) * VV;
            #pragma unroll
            for (int k = 0; k < 13; k++) {
                int i = tid + k*256;
                if (i < RAW_F/4) {
                    int c = i / 50, qq = i - c*50;
                    cp_async16(raw + c*(TTILE*VV) + qq*4, xb + c*(TT*VV) + qq*4);
                }
            }
            CP_COMMIT();
        }

        // ---- FFMA2 mainloop (LDS.128 operand loads; weights from global L1) ----
        u64 acc0[13], acc1[13];
        {
            float b0 = bfs[d0], b1 = bfs[d0+1];
            u64 bb0 = pack2(b0, b0), bb1 = pack2(b1, b1);
            #pragma unroll
            for (int vp = 0; vp < 13; vp++) { acc0[vp] = bb0; acc1[vp] = bb1; }
        }
        #pragma unroll
        for (int cb = 0; cb < CC; cb += 8) {
            float2 wv[8];
            #pragma unroll
            for (int i = 0; i < 8; i++) wv[i] = *(const float2*)(Wg + (cb+i)*DD);
            #pragma unroll
            for (int i = 0; i < 8; i++) {
                u64 s0 = pack2(wv[i].x, wv[i].x);
                u64 s1 = pack2(wv[i].y, wv[i].y);
                const float* ar = At + (cb+i)*ATSTRIDE;
                #pragma unroll
                for (int p = 0; p < 6; p++) {
                    ulonglong2 a2 = ((const ulonglong2*)ar)[p];
                    acc0[2*p]   = ffma2(a2.x, s0, acc0[2*p]);
                    acc1[2*p]   = ffma2(a2.x, s1, acc1[2*p]);
                    acc0[2*p+1] = ffma2(a2.y, s0, acc0[2*p+1]);
                    acc1[2*p+1] = ffma2(a2.y, s1, acc1[2*p+1]);
                }
                u64 a12 = ((const u64*)ar)[12];
                acc0[12] = ffma2(a12, s0, acc0[12]);
                acc1[12] = ffma2(a12, s1, acc1[12]);
            }
        }

        // ---- epilogue: scatter through inverse shift_out into own At region ---
        // (warp-synchronous: all mainloop reads of At precede these writes)
        #pragma unroll
        for (int vp = 0; vp < 13; vp++) {
            float a0, a1, c0, c1;
            unpack2(acc0[vp], a0, a1);
            unpack2(acc1[vp], c0, c1);
            int v = 2*vp;
            int sb = v*DD + d0;
            At[invs[sb]]     = a0;
            At[invs[sb + 1]] = c0;
            if (v + 1 < VV) {
                At[invs[sb + DD]]     = a1;
                At[invs[sb + DD + 1]] = c1;
            }
        }
        __syncthreads();                       // all z-tiles staged

        // stats: thread owns fixed f-slots, accumulate in registers
        #pragma unroll
        for (int k = 0; k < 7; k++) {
            int f = tid + k*256;
            if (f < FEAT) {
                int pa = f + (f >> 6);
                float s = 0.f, q = 0.f;
                #pragma unroll
                for (int w8 = 0; w8 < 8; w8++) {
                    float v = Ats[w8*ATW + pa];
                    s += v; q += v*v;
                }
                rsum[k] += s; rsq[k] += q;
            }
        }
        // transposed coalesced store to g_z [n][d][t][v]
        {
            float* zb = g_z + (size_t)n * (CC*TT*VV) + (size_t)t0 * VV;
            #pragma unroll
            for (int k = 0; k < 13; k++) {
                int qd = tid + k*256;              // quad id, 3200 total
                if (qd < 3200) {
                    int e = qd*4;
                    int d = e / 200;
                    int r = e - d*200;             // multiple of 4, <= 196
                    float4 o;
                    #pragma unroll
                    for (int j = 0; j < 4; j++) {
                        int rr = r + j;
                        int tlj = rr / 25;
                        int vj = rr - tlj*25;
                        ((float*)&o)[j] = Ats[tlj*ATW + vj*65 + d];
                    }
                    *(float4*)(zb + (size_t)d*(TT*VV) + r) = o;
                }
            }
        }
        // loop-top sync protects Ats reuse by next gather
    }
    __syncthreads();
    #pragma unroll
    for (int k = 0; k < 7; k++) {
        int f = tid + k*256;
        if (f < FEAT) {
            atomicAdd(&g_sum[f], rsum[k]);
            atomicAdd(&g_sumsq[f], rsq[k]);
        }
    }
}

// ---------------- kernel 5: finalize BN params (f-space, no indirection) -----
__global__ void finalize_kernel(const float* __restrict__ gamma,
                                const float* __restrict__ beta) {
    int f = blockIdx.x * 256 + threadIdx.x;
    if (f >= FEAT) return;
    const float invn = 1.0f / (float)ROWS;
    float mu = g_sum[f] * invn;
    float var = g_sumsq[f] * invn - mu * mu;
    float sc = gamma[f] * rsqrtf(var + 1e-5f);
    g_scale[f] = sc;
    g_bias[f] = beta[f] - mu * sc;
}

// ---------------- kernel 6: elementwise BN + residual + relu -----------------
// block = (n, d): 6400 contiguous elements; f = v*64+d, v = idx%25.
__global__ void __launch_bounds__(256) final_kernel(const float* __restrict__ x0,
                                                    float* __restrict__ out) {
    __shared__ float sc[VV], bi[VV];
    int b = blockIdx.x;
    int n = b >> 6, d = b & 63;
    int tid = threadIdx.x;
    if (tid < VV) {
        sc[tid] = g_scale[tid*DD + d];
        bi[tid] = g_bias[tid*DD + d];
    }
    __syncthreads();
    size_t base = (size_t)n * (CC*TT*VV) + (size_t)d * (TT*VV);
    const float4* zp = (const float4*)(g_z + base);
    const float4* xp = (const float4*)(x0 + base);
    float4* op = (float4*)(out + base);
    #pragma unroll
    for (int k = 0; k < 7; k++) {
        int q = tid + k*256;
        if (q < (TT*VV)/4) {
            int e = q*4;
            int v0 = e - (e/25)*25;
            float4 z = zp[q], x = xp[q], o;
            #pragma unroll
            for (int j = 0; j < 4; j++) {
                int v = v0 + j; if (v >= VV) v -= VV;
                float val = ((const float*)&z)[j] * sc[v] + bi[v] + ((const float*)&x)[j];
                ((float*)&o)[j] = val > 0.f ? val : 0.f;
            }
            op[q] = o;
        }
    }
}

// ---------------- launcher ---------------------------------------------------
extern "C" void kernel_launch(void* const* d_in, const int* in_sizes, int n_in,
                              void* d_out, int out_size) {
    const float* x0       = (const float*)d_in[0];
    const int*   epoch    = (const int*)  d_in[1];
    const float* fc1_w    = (const float*)d_in[2];
    const float* fc1_b    = (const float*)d_in[3];
    const float* fc2_w    = (const float*)d_in[4];
    const float* fc2_b    = (const float*)d_in[5];
    const float* W        = (const float*)d_in[6];
    const float* b        = (const float*)d_in[7];
    const float* mask     = (const float*)d_in[8];
    const float* gamma    = (const float*)d_in[9];
    const float* beta     = (const float*)d_in[10];
    const int*   shift_in = (const int*)  d_in[11];
    const int*   shift_out= (const int*)  d_in[12];
    float* out = (float*)d_out;

    cudaFuncSetAttribute(gemm_kernel, cudaFuncAttributeMaxDynamicSharedMemorySize, GEMM_SMEM_BYTES);

    pool_kernel<<<NN*CC, 256>>>(x0);
    gate_kernel<<<1, 128>>>(fc1_w, fc1_b, fc2_w, fc2_b, epoch);
    prep_kernel<<<NN + 1, 256>>>(W, b, mask, shift_in, shift_out);
    gemm_kernel<<<NN * 8, 256, GEMM_SMEM_BYTES>>>(x0);
    finalize_kernel<<<(FEAT + 255)/256, 256>>>(gamma, beta);
    final_kernel<<<NN * CC, 256>>>(x0, out);
}

// round 14
// speedup vs baseline: 1.0330x; 1.0330x over previous
#include <cuda_runtime.h>
#include <cuda_bf16.h>
#include <cstdint>

#define NN 128
#define CC 64
#define TT 256
#define VV 25
#define DD 64
#define RR 16
#define FEAT 1600
#define ROWS (NN*TT)
#define TTILE 8                 // frames per tile (warp = frame)
#define NTILES 4                // tiles per block (32 frames)
#define BUFW 1664               // epilogue buffer stride per frame (floats)
#define WROW 72                 // bf16 row stride for A/W tiles (144B, 16B-aligned)

typedef unsigned long long u64;

// smem byte offsets (16B-aligned)
#define O_RAW 0                 // 12800 floats = 51200 B
#define O_ATS 51200             // 8 warps x (Ah 4608B + Al 4608B) = 73728 B
#define O_BUF O_ATS             // alias: 8 x 1664 x 4 = 53248 B <= 73728
#define O_WTH 124928            // 64 x 144 = 9216 B
#define O_WTL 134144            // 9216 B
#define O_IV  143360            // 2048 shorts = 4096 B
#define O_BFS 147456            // 64 floats = 256 B
#define SM_BYTES 147712

// ---------------- device scratch ---------------------------------------------
__device__ float g_pooled[NN*CC];
__device__ float g_gate[NN*4];
__device__ float g_bf[NN*DD];
__device__ __nv_bfloat16 g_Wsp[NN*2*DD*WROW];   // [n][hi/lo][d][72] W^T bf16 split
__device__ float g_z[(size_t)NN*CC*TT*VV];      // pre-BN z, [n][d][t][v]
__device__ float g_sum[FEAT];
__device__ float g_sumsq[FEAT];
__device__ float g_scale[FEAT];
__device__ float g_bias[FEAT];
__device__ float4 g_tp4[1024];                  // [(c/2)][v32]: {tm0, src0, tm1, src1}
__device__ short g_iv2[2048];                   // [d][v32]: y(v,d) -> buf slot f+(f>>6)

// ---------------- helpers ----------------------------------------------------
__device__ __forceinline__ uint32_t smem_u32(const void* p) {
    uint32_t a;
    asm("{ .reg .u64 t; cvta.to.shared.u64 t, %1; cvt.u32.u64 %0, t; }" : "=r"(a) : "l"(p));
    return a;
}
__device__ __forceinline__ void ldm4(uint32_t addr, uint32_t* r) {
    asm volatile("ldmatrix.sync.aligned.m8n8.x4.shared.b16 {%0,%1,%2,%3}, [%4];"
        : "=r"(r[0]), "=r"(r[1]), "=r"(r[2]), "=r"(r[3]) : "r"(addr));
}
__device__ __forceinline__ void mma16816(float* c, const uint32_t* a, const uint32_t* b) {
    asm volatile("mma.sync.aligned.m16n8k16.row.col.f32.bf16.bf16.f32 "
        "{%0,%1,%2,%3}, {%4,%5,%6,%7}, {%8,%9}, {%0,%1,%2,%3};"
        : "+f"(c[0]), "+f"(c[1]), "+f"(c[2]), "+f"(c[3])
        : "r"(a[0]), "r"(a[1]), "r"(a[2]), "r"(a[3]), "r"(b[0]), "r"(b[1]));
}
__device__ __forceinline__ void cp_async16(uint32_t dst, const void* src) {
    asm volatile("cp.async.cg.shared.global [%0], [%1], 16;" :: "r"(dst), "l"(src));
}
#define CP_COMMIT() asm volatile("cp.async.commit_group;")
#define CP_WAIT0()  asm volatile("cp.async.wait_group 0;")
__device__ __forceinline__ uint32_t packbf(__nv_bfloat16 a, __nv_bfloat16 b) {
    return (uint32_t)__bfloat16_as_ushort(a) | ((uint32_t)__bfloat16_as_ushort(b) << 16);
}

// ---------------- kernel 1: pool ---------------------------------------------
__global__ void pool_kernel(const float* __restrict__ x0) {
    int nc = blockIdx.x;
    const float4* p = (const float4*)(x0 + (size_t)nc * (TT*VV));
    float s = 0.f;
    for (int i = threadIdx.x; i < (TT*VV)/4; i += 256) {
        float4 v = p[i]; s += v.x + v.y + v.z + v.w;
    }
    for (int off = 16; off > 0; off >>= 1) s += __shfl_down_sync(0xffffffffu, s, off);
    __shared__ float red[8];
    int w = threadIdx.x >> 5, l = threadIdx.x & 31;
    if (l == 0) red[w] = s;
    __syncthreads();
    if (threadIdx.x == 0) {
        float t = 0.f;
        #pragma unroll
        for (int i = 0; i < 8; i++) t += red[i];
        g_pooled[nc] = t * (1.f / (TT*VV));
    }
}

// ---------------- kernel 2: SE gate ------------------------------------------
__global__ void gate_kernel(const float* __restrict__ fc1_w, const float* __restrict__ fc1_b,
                            const float* __restrict__ fc2_w, const float* __restrict__ fc2_b,
                            const int* __restrict__ epoch_p) {
    int n = threadIdx.x;
    if (n >= NN) return;
    float pooled[CC];
    #pragma unroll
    for (int c = 0; c < CC; c++) pooled[c] = g_pooled[n*CC + c];
    float h[RR];
    #pragma unroll
    for (int j = 0; j < RR; j++) {
        float s = fc1_b[j];
        #pragma unroll
        for (int c = 0; c < CC; c++) s += pooled[c] * fc1_w[j*CC + c];
        h[j] = s > 0.f ? s : 0.f;
    }
    float lg[4];
    #pragma unroll
    for (int k = 0; k < 4; k++) {
        float s = fc2_b[k];
        #pragma unroll
        for (int j = 0; j < RR; j++) s += h[j] * fc2_w[k*RR + j];
        lg[k] = s;
    }
    int ep = *epoch_p;
    float tao = (ep >= 60) ? 1.0f : (-(29.0f/60.0f)*(float)ep + 30.0f);
    float inv = 1.0f / tao;
    float m = fmaxf(fmaxf(lg[0], lg[1]), fmaxf(lg[2], lg[3]));
    float e[4], sum = 0.f;
    #pragma unroll
    for (int k = 0; k < 4; k++) { e[k] = __expf((lg[k]-m)*inv); sum += e[k]; }
    float r = 1.0f / sum;
    #pragma unroll
    for (int k = 0; k < 4; k++) g_gate[n*4 + k] = e[k]*r;
}

// ---------------- kernel 3: prep (fused W^T split + tables + zero stats) -----
__global__ void prep_kernel(const float* __restrict__ W, const float* __restrict__ b,
                            const float* __restrict__ mask, const int* __restrict__ shift_in,
                            const int* __restrict__ shift_out) {
    int blk = blockIdx.x, tid = threadIdx.x;
    if (blk < NN) {
        int n = blk;
        float g0 = g_gate[n*4+0], g1 = g_gate[n*4+1], g2 = g_gate[n*4+2], g3 = g_gate[n*4+3];
        __nv_bfloat16* wsp = g_Wsp + (size_t)n * (2*DD*WROW);
        for (int i = tid; i < CC*DD; i += 256) {
            int c = i >> 6, d = i & 63;          // read W gated at (c,d)
            int cd = c*DD + d;
            float wv = g0*W[cd] + g1*W[CC*DD+cd] + g2*W[2*CC*DD+cd] + g3*W[3*CC*DD+cd];
            __nv_bfloat16 hb = __float2bfloat16(wv);
            __nv_bfloat16 lb = __float2bfloat16(wv - __bfloat162float(hb));
            wsp[d*WROW + c] = hb;                // W^T hi: [d][c]
            wsp[DD*WROW + d*WROW + c] = lb;      // W^T lo
        }
        if (tid < DD)
            g_bf[n*DD + tid] = g0*b[tid] + g1*b[DD+tid] + g2*b[2*DD+tid] + g3*b[3*DD+tid];
    } else {
        for (int j = tid; j < 1024; j += 256) {  // [(c/2)][v32]
            int cp2 = j >> 5, v = j & 31;
            int c0 = 2*cp2, c1 = c0 + 1;
            float4 rec;
            if (v < VV) {
                int s0 = shift_in[v*CC + c0];
                int s1 = shift_in[v*CC + c1];
                rec.x = tanhf(mask[v*CC + c0]) + 1.0f;
                rec.y = __int_as_float((s0 & 63)*200 + (s0 >> 6));
                rec.z = tanhf(mask[v*CC + c1]) + 1.0f;
                rec.w = __int_as_float((s1 & 63)*200 + (s1 >> 6));
            } else {
                rec.x = 0.f; rec.y = __int_as_float(0);
                rec.z = 0.f; rec.w = __int_as_float(0);
            }
            g_tp4[j] = rec;
        }
        for (int f = tid; f < FEAT; f += 256) {
            g_sum[f] = 0.f; g_sumsq[f] = 0.f;
            int s = shift_out[f];
            g_iv2[(s & 63)*32 + (s >> 6)] = (short)(f + (f >> 6));
        }
    }
}

// ---------------- kernel 4: bf16 mma.sync GEMM + scatter + stats -------------
// 1024 blocks = (n, q8 of 32 frames); 4 tiles of 8 frames; warp = frame.
__global__ void __launch_bounds__(256, 1) gemm_kernel(const float* __restrict__ x0) {
    extern __shared__ __align__(16) char sm[];
    float* raw = (float*)(sm + O_RAW);           // [c][200]
    float* buf = (float*)(sm + O_BUF);
    short* iv2 = (short*)(sm + O_IV);
    float* bfs = (float*)(sm + O_BFS);
    uint32_t sb = smem_u32(sm);

    int bid = blockIdx.x;
    int n = bid >> 3, q8 = bid & 7;
    int tid = threadIdx.x;
    int w = tid >> 5, l = tid & 31;

    // stage: Wt hi/lo (cp.async), iv2, bfs; prefetch raw tile 0
    {
        const __nv_bfloat16* wsp = g_Wsp + (size_t)n * (2*DD*WROW);
        for (int i = tid; i < 576; i += 256)     // 9216B hi
            cp_async16(sb + O_WTH + i*16, (const char*)wsp + i*16);
        for (int i = tid; i < 576; i += 256)     // 9216B lo
            cp_async16(sb + O_WTL + i*16, (const char*)wsp + DD*WROW*2 + i*16);
        for (int j = tid; j < 2048; j += 256) iv2[j] = g_iv2[j];
        if (tid < DD) bfs[tid] = g_bf[n*DD + tid];
    }
    const float* xbase = x0 + (size_t)n * CC * (TT*VV) + (size_t)(q8*32) * VV;
    {
        #pragma unroll
        for (int k = 0; k < 13; k++) {
            int i = tid + k*256;
            if (i < 3200) {
                int c = i / 50, q = i - c*50;
                cp_async16(sb + O_RAW + (c*200 + q*4)*4, xbase + (size_t)c*(TT*VV) + q*4);
            }
        }
        CP_COMMIT();
    }

    uint32_t AhU = sb + O_ATS + w*9216;
    uint32_t AlU = AhU + 4608;
    uint32_t WhU = sb + O_WTH;
    uint32_t WlU = sb + O_WTL;
    uint32_t* AhW = (uint32_t*)(sm + O_ATS + w*9216);
    uint32_t* AlW = (uint32_t*)(sm + O_ATS + w*9216 + 4608);
    const float* rw = raw + w*VV;

    int g = l >> 2, t2 = (l & 3) * 2;

    float rsum[7], rsq[7];
    #pragma unroll
    for (int k = 0; k < 7; k++) { rsum[k] = 0.f; rsq[k] = 0.f; }

    for (int it = 0; it < NTILES; it++) {
        int t0 = q8*32 + it*TTILE;
        CP_WAIT0();
        __syncthreads();                          // raw ready; buf consumed

        // ---- gather + bf16 split into Ah/Al [v][c] (lane = v) ----
        if (l < VV) {
            #pragma unroll 8
            for (int i = 0; i < 32; i++) {
                float4 t = g_tp4[i*32 + l];
                float v0 = rw[__float_as_int(t.y)] * t.x;
                float v1 = rw[__float_as_int(t.w)] * t.z;
                __nv_bfloat16 h0 = __float2bfloat16(v0);
                __nv_bfloat16 h1 = __float2bfloat16(v1);
                __nv_bfloat16 L0 = __float2bfloat16(v0 - __bfloat162float(h0));
                __nv_bfloat16 L1 = __float2bfloat16(v1 - __bfloat162float(h1));
                AhW[l*36 + i] = packbf(h0, h1);
                AlW[l*36 + i] = packbf(L0, L1);
            }
        }
        __syncthreads();                          // raw consumed by all warps

        // prefetch next raw tile (overlaps mma)
        if (it + 1 < NTILES) {
            const float* xb = xbase + (size_t)(it + 1) * (TTILE*VV);
            #pragma unroll
            for (int k = 0; k < 13; k++) {
                int i = tid + k*256;
                if (i < 3200) {
                    int c = i / 50, q = i - c*50;
                    cp_async16(sb + O_RAW + (c*200 + q*4)*4, xb + (size_t)c*(TT*VV) + q*4);
                }
            }
            CP_COMMIT();
        }

        // ---- mma chain: acc(bias) += Ah*Wh + Ah*Wl + Al*Wh ----
        float acc[64];                            // [mi][nb][4]
        #pragma unroll
        for (int mi = 0; mi < 2; mi++)
            #pragma unroll
            for (int nb = 0; nb < 8; nb++) {
                float b0 = bfs[nb*8 + t2], b1 = bfs[nb*8 + t2 + 1];
                float* a = acc + (mi*8 + nb)*4;
                a[0] = b0; a[1] = b1; a[2] = b0; a[3] = b1;
            }
        #pragma unroll
        for (int kk = 0; kk < 4; kk++) {
            int rA = l & 15, hA = l >> 4;
            uint32_t aoff = (uint32_t)(rA*144 + kk*32 + hA*16);
            uint32_t ah0[4], ah1[4], al0[4], al1[4];
            ldm4(AhU + aoff, ah0);
            ldm4(AhU + 16*144 + aoff, ah1);
            ldm4(AlU + aoff, al0);
            ldm4(AlU + 16*144 + aoff, al1);
            int rB = l & 7, kb = (l >> 3) & 1, nh = (l >> 4) & 1;
            #pragma unroll
            for (int p = 0; p < 4; p++) {
                uint32_t boff = (uint32_t)((p*16 + rB + nh*8)*144 + kk*32 + kb*16);
                uint32_t bh[4], bl[4];
                ldm4(WhU + boff, bh);
                ldm4(WlU + boff, bl);
                #pragma unroll
                for (int mi = 0; mi < 2; mi++) {
                    const uint32_t* am = mi ? ah1 : ah0;
                    const uint32_t* al = mi ? al1 : al0;
                    float* c0 = acc + (mi*8 + 2*p)*4;
                    float* c1 = acc + (mi*8 + 2*p + 1)*4;
                    mma16816(c0, am, bh);     mma16816(c1, am, bh + 2);
                    mma16816(c0, am, bl);     mma16816(c1, am, bl + 2);
                    mma16816(c0, al, bh);     mma16816(c1, al, bh + 2);
                }
            }
        }
        __syncthreads();                          // all At reads done; buf writable

        // ---- epilogue: scatter accs through iv2 into own frame strip ----
        {
            float* strip = buf + w*BUFW;
            #pragma unroll
            for (int mi = 0; mi < 2; mi++) {
                int v0r = mi*16 + g;              // <= 23, always valid
                int v1r = v0r + 8;
                #pragma unroll
                for (int nb = 0; nb < 8; nb++) {
                    const float* a = acc + (mi*8 + nb)*4;
                    int d = nb*8 + t2;
                    strip[iv2[d*32 + v0r]]     = a[0];
                    strip[iv2[(d+1)*32 + v0r]] = a[1];
                    if (v1r < VV) {
                        strip[iv2[d*32 + v1r]]     = a[2];
                        strip[iv2[(d+1)*32 + v1r]] = a[3];
                    }
                }
            }
        }
        __syncthreads();                          // buf fully staged

        // ---- stats: thread owns fixed f-slots ----
        #pragma unroll
        for (int k = 0; k < 7; k++) {
            int f = tid + k*256;
            if (f < FEAT) {
                int pa = f + (f >> 6);
                float s = 0.f, q = 0.f;
                #pragma unroll
                for (int w8 = 0; w8 < 8; w8++) {
                    float v = buf[w8*BUFW + pa];
                    s += v; q += v*v;
                }
                rsum[k] += s; rsq[k] += q;
            }
        }
        // ---- coalesced transposed z store [n][d][t0..t0+7][v] ----
        {
            float* zb = g_z + (size_t)n * (CC*TT*VV) + (size_t)t0 * VV;
            #pragma unroll
            for (int k = 0; k < 13; k++) {
                int qd = tid + k*256;
                if (qd < 3200) {
                    int e = qd*4;
                    int d = e / 200;
                    int r = e - d*200;
                    float4 o;
                    #pragma unroll
                    for (int j = 0; j < 4; j++) {
                        int rr = r + j;
                        int tl = rr / 25, v = rr - tl*25;
                        ((float*)&o)[j] = buf[tl*BUFW + v*65 + d];
                    }
                    *(float4*)(zb + (size_t)d*(TT*VV) + r) = o;
                }
            }
        }
        // loop-top sync protects raw/buf reuse
    }
    __syncthreads();
    #pragma unroll
    for (int k = 0; k < 7; k++) {
        int f = tid + k*256;
        if (f < FEAT) {
            atomicAdd(&g_sum[f], rsum[k]);
            atomicAdd(&g_sumsq[f], rsq[k]);
        }
    }
}

// ---------------- kernel 5: finalize (f-space) -------------------------------
__global__ void finalize_kernel(const float* __restrict__ gamma,
                                const float* __restrict__ beta) {
    int f = blockIdx.x*256 + threadIdx.x;
    if (f >= FEAT) return;
    const float invn = 1.0f / (float)ROWS;
    float mu = g_sum[f] * invn;
    float var = g_sumsq[f] * invn - mu*mu;
    float sc = gamma[f] * rsqrtf(var + 1e-5f);
    g_scale[f] = sc;
    g_bias[f] = beta[f] - mu*sc;
}

// ---------------- kernel 6: elementwise BN + residual + relu -----------------
__global__ void __launch_bounds__(256) final_kernel(const float* __restrict__ x0,
                                                    float* __restrict__ out) {
    __shared__ float sc[VV], bi[VV];
    int b = blockIdx.x;
    int n = b >> 6, d = b & 63;
    int tid = threadIdx.x;
    if (tid < VV) { sc[tid] = g_scale[tid*DD + d]; bi[tid] = g_bias[tid*DD + d]; }
    __syncthreads();
    size_t base = (size_t)n * (CC*TT*VV) + (size_t)d * (TT*VV);
    const float4* zp = (const float4*)(g_z + base);
    const float4* xp = (const float4*)(x0 + base);
    float4* op = (float4*)(out + base);
    #pragma unroll
    for (int k = 0; k < 7; k++) {
        int q = tid + k*256;
        if (q < (TT*VV)/4) {
            int e = q*4;
            int v0 = e - (e/25)*25;
            float4 z = zp[q], x = xp[q], o;
            #pragma unroll
            for (int j = 0; j < 4; j++) {
                int v = v0 + j; if (v >= VV) v -= VV;
                float val = ((const float*)&z)[j]*sc[v] + bi[v] + ((const float*)&x)[j];
                ((float*)&o)[j] = val > 0.f ? val : 0.f;
            }
            op[q] = o;
        }
    }
}

// ---------------- launcher ---------------------------------------------------
extern "C" void kernel_launch(void* const* d_in, const int* in_sizes, int n_in,
                              void* d_out, int out_size) {
    const float* x0       = (const float*)d_in[0];
    const int*   epoch    = (const int*)  d_in[1];
    const float* fc1_w    = (const float*)d_in[2];
    const float* fc1_b    = (const float*)d_in[3];
    const float* fc2_w    = (const float*)d_in[4];
    const float* fc2_b    = (const float*)d_in[5];
    const float* W        = (const float*)d_in[6];
    const float* b        = (const float*)d_in[7];
    const float* mask     = (const float*)d_in[8];
    const float* gamma    = (const float*)d_in[9];
    const float* beta     = (const float*)d_in[10];
    const int*   shift_in = (const int*)  d_in[11];
    const int*   shift_out= (const int*)  d_in[12];
    float* out = (float*)d_out;

    cudaFuncSetAttribute(gemm_kernel, cudaFuncAttributeMaxDynamicSharedMemorySize, SM_BYTES);

    pool_kernel<<<NN*CC, 256>>>(x0);
    gate_kernel<<<1, 128>>>(fc1_w, fc1_b, fc2_w, fc2_b, epoch);
    prep_kernel<<<NN + 1, 256>>>(W, b, mask, shift_in, shift_out);
    gemm_kernel<<<NN*8, 256, SM_BYTES>>>(x0);
    finalize_kernel<<<(FEAT + 255)/256, 256>>>(gamma, beta);
    final_kernel<<<NN*CC, 256>>>(x0, out);
}